// round 17
// baseline (speedup 1.0000x reference)
#include <cuda_runtime.h>
#include <cuda_bf16.h>
#include <cstdint>

#define N_TOTAL 8388608   // 2^23
#define NB 148             // persistent blocks (<= SM count -> all resident)

__device__ float2 g_scratch[N_TOTAL];   // transposed intermediate
__device__ int g_bar;                    // monotonic barrier ticket counter

__host__ __device__ __forceinline__ constexpr int brev_c(int x, int K) {
    int r = 0;
    for (int b = 0; b < K; b++) r |= ((x >> b) & 1) << (K - 1 - b);
    return r;
}

__device__ __forceinline__ float2 cmul(float2 a, float2 w) {
    return make_float2(a.x * w.x - a.y * w.y, a.x * w.y + a.y * w.x);
}

// Full-prefetch in-register DIF butterfly network, K stages at offset S0.
template <int S0, int K>
__device__ __forceinline__ void bnet_pf(float2* a, unsigned jj,
                                        const float2* __restrict__ W) {
    float2 tw[(1 << K) - 1];
#pragma unroll
    for (int u = 0; u < K; u++)
#pragma unroll
        for (int c = 0; c < (1 << u); c++)
            tw[(1 << u) - 1 + c] =
                __ldg(&W[(jj << (22 - S0 - u)) + ((unsigned)c << (22 - u))]);
#pragma unroll
    for (int u = 0; u < K; u++) {
        const int half = 1 << (K - 1 - u);
#pragma unroll
        for (int t = 0; t < (1 << K) / 2; t++) {
            const int q1 = ((t & ~(half - 1)) << 1) | (t & (half - 1));
            const int q2 = q1 + half;
            const int c = brev_c(q1, K) & ((1 << u) - 1);
            float2 w = tw[(1 << u) - 1 + c];
            float2 p = cmul(a[q2], w);
            float2 tt = a[q1];
            a[q1] = make_float2(tt.x + p.x, tt.y + p.y);
            a[q2] = make_float2(tt.x - p.x, tt.y - p.y);
        }
    }
}

// kA round 1 (S0=0, K=4, jj=0) specialized for REAL inputs: stage 0 done in
// real arithmetic, stages 1..3 full complex.
__device__ __forceinline__ void bnetA_r1(const float* ar, float2* a,
                                         const float2* __restrict__ W) {
    float2 w0 = __ldg(&W[0]);
    float2 tw[15];
#pragma unroll
    for (int u = 1; u < 4; u++)
#pragma unroll
        for (int c = 0; c < (1 << u); c++)
            tw[(1 << u) - 1 + c] = __ldg(&W[(unsigned)c << (22 - u)]);
    // stage 0: pairs (t, t+8), inputs real, c=0
#pragma unroll
    for (int t = 0; t < 8; t++) {
        float pr = ar[t + 8] * w0.x;
        float pi = ar[t + 8] * w0.y;
        a[t] = make_float2(ar[t] + pr, pi);
        a[t + 8] = make_float2(ar[t] - pr, -pi);
    }
    // stages 1..3
#pragma unroll
    for (int u = 1; u < 4; u++) {
        const int half = 1 << (3 - u);
#pragma unroll
        for (int t = 0; t < 8; t++) {
            const int q1 = ((t & ~(half - 1)) << 1) | (t & (half - 1));
            const int q2 = q1 + half;
            const int c = brev_c(q1, 4) & ((1 << u) - 1);
            float2 w = tw[(1 << u) - 1 + c];
            float2 p = cmul(a[q2], w);
            float2 tt = a[q1];
            a[q1] = make_float2(tt.x + p.x, tt.y + p.y);
            a[q2] = make_float2(tt.x - p.x, tt.y - p.y);
        }
    }
}

#define SMEM_ELEMS 16384
#define SMEM_BYTES (SMEM_ELEMS * 8)

__device__ __forceinline__ unsigned phA(unsigned q, unsigned g) {
    unsigned l = (q << 3) | g;
    return l ^ (((l >> 6) & 1u) << 3);
}
__device__ __forceinline__ unsigned phB(unsigned q, unsigned js) {
    unsigned l = (q << 2) | js;
    return l ^ ((l >> 4) & 3u) ^ (((l >> 6) & 3u) << 2);
}

// Replay-safe grid barrier: monotonic ticket counter, no reset needed.
// Valid because all NB blocks are co-resident (1 CTA/SM, NB <= #SM).
__device__ __forceinline__ void grid_barrier() {
    __syncthreads();
    if (threadIdx.x == 0) {
        __threadfence();
        int ticket = atomicAdd(&g_bar, 1);
        int target = (ticket / NB + 1) * NB;
        while (*(volatile int*)&g_bar < target) {}
        __threadfence();
    }
    __syncthreads();
}

// ============================================================================
// Fused persistent kernel: phase A (stages 0..10) tiles, grid barrier,
// phase B (stages 11..22) tiles. Per-tile bodies R10-identical.
// ============================================================================
__global__ void __launch_bounds__(512, 1)
fft_fused(const float* __restrict__ Xr, const float2* __restrict__ W,
          float2* __restrict__ Scr, float2* __restrict__ Out) {
    extern __shared__ float2 sm2[];
    const unsigned t = threadIdx.x;

    // ---------------- phase A: stages [0,11), tiles = 8 bases x 2048 q ------
    {
        const unsigned g = t & 7u;
        const unsigned rest = t >> 3;
        for (unsigned ta = blockIdx.x; ta < 512u; ta += NB) {
            const unsigned base = ta * 8u + g;
            __syncthreads();   // prior tile's smem reads complete

            // round 1: bits q[10:7], S0=0, jj=0; real-input specialization
#pragma unroll
            for (int pass = 0; pass < 2; pass++) {
                unsigned low7 = rest + 64u * pass;
                float ar[16];
                float2 a[16];
#pragma unroll
                for (int x = 0; x < 16; x++)
                    ar[x] = __ldg(&Xr[base + ((((unsigned)x << 7) | low7) << 12)]);
                bnetA_r1(ar, a, W);
#pragma unroll
                for (int x = 0; x < 16; x++)
                    sm2[phA(((unsigned)x << 7) | low7, g)] = a[x];
            }
            __syncthreads();

            // round 2: bits q[6:3], S0=4, jj = brev4(q[10:7])
#pragma unroll
            for (int pass = 0; pass < 2; pass++) {
                unsigned idx2 = rest + 64u * pass;
                unsigned lo3 = idx2 & 7u;
                unsigned H = idx2 >> 3;
                unsigned jj = __brev(H) >> 28;
                float2 a[16];
#pragma unroll
                for (int x = 0; x < 16; x++)
                    a[x] = sm2[phA((H << 7) | ((unsigned)x << 3) | lo3, g)];
                bnet_pf<4, 4>(a, jj, W);
#pragma unroll
                for (int x = 0; x < 16; x++)
                    sm2[phA((H << 7) | ((unsigned)x << 3) | lo3, g)] = a[x];
            }
            __syncthreads();

            // round 3: bits q[2:0], S0=8, jj = brev8(q[10:3]); transposed store
#pragma unroll
            for (int pass = 0; pass < 4; pass++) {
                unsigned B = rest + 64u * pass;
                unsigned jj = __brev(B) >> 24;
                float2 a[8];
#pragma unroll
                for (int x = 0; x < 8; x++)
                    a[x] = sm2[phA((B << 3) | (unsigned)x, g)];
                bnet_pf<8, 3>(a, jj, W);
#pragma unroll
                for (int x = 0; x < 8; x++) {
                    unsigned C = ((unsigned)brev_c(x, 3) << 8) | jj;
                    Scr[C * 4096u + base] = a[x];
                }
            }
        }
    }

    grid_barrier();

    // ---------------- phase B: stages [11,23), tiles = 4 j x 4096 q ---------
    {
        const unsigned jg = t & 3u;
        const unsigned rest = t >> 2;
        const unsigned jg1 = t >> 7;
        const unsigned lowt = t & 127u;
        for (unsigned tb = blockIdx.x; tb < 512u; tb += NB) {
            const unsigned j0 = tb * 4u;
            __syncthreads();

            // round 1: bits q[11:8], S0=11. Warp-uniform jB, coalesced loads.
            {
                const unsigned jB1 = j0 + jg1;
#pragma unroll
                for (int pass = 0; pass < 2; pass++) {
                    unsigned low8 = lowt + 128u * pass;
                    float2 a[16];
#pragma unroll
                    for (int x = 0; x < 16; x++)
                        a[x] = __ldcs(&Scr[jB1 * 4096u +
                                           (((unsigned)x << 8) | low8)]);
                    bnet_pf<11, 4>(a, jB1, W);
#pragma unroll
                    for (int x = 0; x < 16; x++)
                        sm2[phB(((unsigned)x << 8) | low8, jg1)] = a[x];
                }
            }
            __syncthreads();

            const unsigned jB = j0 + jg;

            // round 2: bits q[7:4], S0=15, jj = jB + brev4(q[11:8])<<11
#pragma unroll
            for (int pass = 0; pass < 2; pass++) {
                unsigned idx2 = rest + 128u * pass;
                unsigned lo4 = idx2 & 15u;
                unsigned H = idx2 >> 4;
                unsigned jj = jB + ((__brev(H) >> 28) << 11);
                float2 a[16];
#pragma unroll
                for (int x = 0; x < 16; x++)
                    a[x] = sm2[phB((H << 8) | ((unsigned)x << 4) | lo4, jg)];
                bnet_pf<15, 4>(a, jj, W);
#pragma unroll
                for (int x = 0; x < 16; x++)
                    sm2[phB((H << 8) | ((unsigned)x << 4) | lo4, jg)] = a[x];
            }
            __syncthreads();

            // round 3: bits q[3:0], S0=19, jj = jB + brev8(q[11:4])<<11
#pragma unroll
            for (int pass = 0; pass < 2; pass++) {
                unsigned B = rest + 128u * pass;
                unsigned Brev = __brev(B) >> 24;
                unsigned jj = jB + (Brev << 11);
                float2 a[16];
#pragma unroll
                for (int x = 0; x < 16; x++)
                    a[x] = sm2[phB((B << 4) | (unsigned)x, jg)];
                bnet_pf<19, 4>(a, jj, W);
#pragma unroll
                for (int x = 0; x < 16; x++) {
                    unsigned C = ((unsigned)brev_c(x, 4) << 8) | Brev;
                    __stcs(&Out[(C << 11) + jB], a[x]);
                }
            }
        }
    }
}

// ---------------------------------------------------------------------------
extern "C" void kernel_launch(void* const* d_in, const int* in_sizes, int n_in,
                              void* d_out, int out_size) {
    const float* inp = (const float*)d_in[0];
    const float2* w = (const float2*)d_in[1];
    float2* out = (float2*)d_out;

    float2* scr = nullptr;
    cudaGetSymbolAddress((void**)&scr, g_scratch);

    cudaFuncSetAttribute(fft_fused, cudaFuncAttributeMaxDynamicSharedMemorySize,
                         SMEM_BYTES);

    fft_fused<<<NB, 512, SMEM_BYTES>>>(inp, w, scr, out);
}